// round 2
// baseline (speedup 1.0000x reference)
#include <cuda_runtime.h>
#include <cuda_bf16.h>
#include <mma.h>
using namespace nvcuda;

#define BWIN 1024
#define NHD  16
#define NTOK 64
#define HD   32
#define CDIM 512
#define MROWS (BWIN*NTOK)   // 65536

// ---------------- scratch (device globals; no runtime alloc allowed) ----------------
__device__ float g_Q[BWIN*NHD*NTOK*HD];     // (b, h, n, d)
__device__ float g_K[BWIN*NHD*NTOK*HD];
__device__ float g_V[BWIN*NHD*NTOK*HD];
__device__ float g_attn[(size_t)MROWS*CDIM];// (b*64+n, h*32+d)
__device__ float g_table[225*NHD];
__device__ float g_bias[NHD*NTOK*NTOK];     // (h, n, m) = 16*sigmoid(table[idx])

// ---------------- kernel 1: CPB MLP -> table (225, 16) ----------------
__global__ void cpb_kernel(const float* __restrict__ rct, const float* __restrict__ w1,
                           const float* __restrict__ b1, const float* __restrict__ w2)
{
    __shared__ float hid[512];
    int t = blockIdx.x;                       // 0..224
    float c0 = rct[t*2], c1 = rct[t*2+1];
    for (int j = threadIdx.x; j < 512; j += blockDim.x) {
        float hv = c0*w1[j*2] + c1*w1[j*2+1] + b1[j];
        hid[j] = hv > 0.f ? hv : 0.f;
    }
    __syncthreads();
    int warp = threadIdx.x >> 5, lane = threadIdx.x & 31;
    for (int h = warp; h < NHD; h += 8) {
        float s = 0.f;
        for (int j = lane; j < 512; j += 32) s += hid[j]*w2[h*512 + j];
        #pragma unroll
        for (int o = 16; o; o >>= 1) s += __shfl_xor_sync(0xffffffffu, s, o);
        if (lane == 0) g_table[t*NHD + h] = s;
    }
}

// ---------------- kernel 2: rel-pos bias (16, 64, 64) ----------------
__global__ void bias_kernel(const int* __restrict__ idx)
{
    int i = blockIdx.x*blockDim.x + threadIdx.x;   // 0..65535
    int h = i >> 12;
    int nm = i & 4095;
    float v = g_table[idx[nm]*NHD + h];
    g_bias[i] = 16.f / (1.f + __expf(-v));
}

// ---------------- 3xTF32 GEMM: C(M,N) = A(M,512) * Bw(N,512)^T ----------------
// Error-compensated TF32: x = hi + lo (both tf32); A*B ~= Ah*Bh + Al*Bh + Ah*Bl
// MODE 0: qkv -> scatter to g_Q/g_K/g_V with [q_bias, 0, v_bias]
// MODE 1: proj -> Cout + b0
template<int MODE>
__global__ __launch_bounds__(256) void gemm128(const float* __restrict__ A_in,
        const float* __restrict__ Bw, const float* __restrict__ b0,
        const float* __restrict__ b2, float* __restrict__ Cout)
{
    __shared__ float As[128][36];
    __shared__ float Bs[128][36];
    __shared__ float Cs[8][16][16];

    const float* A = (MODE == 1) ? (const float*)g_attn : A_in;

    const int tid  = threadIdx.x;
    const int warp = tid >> 5, lane = tid & 31;
    const int warpM = warp >> 2, warpN = warp & 3;     // 2 x 4 warp grid
    const int m0 = blockIdx.y * 128;
    const int n0 = blockIdx.x * 128;

    wmma::fragment<wmma::accumulator,16,16,8,float> acc[4][2];
    #pragma unroll
    for (int i=0;i<4;i++)
        #pragma unroll
        for (int j=0;j<2;j++) wmma::fill_fragment(acc[i][j], 0.f);

    for (int kt = 0; kt < 512; kt += 32) {
        #pragma unroll
        for (int i = 0; i < 4; i++) {
            int id = tid + i*256;          // 0..1023 float4 slots
            int r  = id >> 3, c4 = (id & 7) << 2;
            *(float4*)&As[r][c4] = *(const float4*)&A [(size_t)(m0+r)*512 + kt + c4];
            *(float4*)&Bs[r][c4] = *(const float4*)&Bw[(size_t)(n0+r)*512 + kt + c4];
        }
        __syncthreads();
        #pragma unroll
        for (int kk = 0; kk < 32; kk += 8) {
            wmma::fragment<wmma::matrix_a,16,16,8,wmma::precision::tf32,wmma::row_major> ah[4], al[4];
            wmma::fragment<wmma::matrix_b,16,16,8,wmma::precision::tf32,wmma::col_major> bh[2], bl[2];
            #pragma unroll
            for (int i = 0; i < 4; i++) {
                wmma::load_matrix_sync(ah[i], &As[warpM*64 + i*16][kk], 36);
                #pragma unroll
                for (int t = 0; t < ah[i].num_elements; t++) {
                    float o  = ah[i].x[t];
                    float hi = wmma::__float_to_tf32(o);
                    ah[i].x[t] = hi;
                    al[i].x[t] = wmma::__float_to_tf32(o - hi);
                }
            }
            #pragma unroll
            for (int j = 0; j < 2; j++) {
                wmma::load_matrix_sync(bh[j], &Bs[warpN*32 + j*16][kk], 36);
                #pragma unroll
                for (int t = 0; t < bh[j].num_elements; t++) {
                    float o  = bh[j].x[t];
                    float hi = wmma::__float_to_tf32(o);
                    bh[j].x[t] = hi;
                    bl[j].x[t] = wmma::__float_to_tf32(o - hi);
                }
            }
            #pragma unroll
            for (int i = 0; i < 4; i++)
                #pragma unroll
                for (int j = 0; j < 2; j++) {
                    wmma::mma_sync(acc[i][j], al[i], bh[j], acc[i][j]);
                    wmma::mma_sync(acc[i][j], ah[i], bl[j], acc[i][j]);
                    wmma::mma_sync(acc[i][j], ah[i], bh[j], acc[i][j]);
                }
        }
        __syncthreads();
    }

    // epilogue: per-warp patch, then scatter/store
    #pragma unroll
    for (int i = 0; i < 4; i++)
        #pragma unroll
        for (int j = 0; j < 2; j++) {
            wmma::store_matrix_sync(&Cs[warp][0][0], acc[i][j], 16, wmma::mem_row_major);
            __syncwarp();
            int row0 = m0 + warpM*64 + i*16;
            int col0 = n0 + warpN*32 + j*16;
            #pragma unroll
            for (int e = lane; e < 256; e += 32) {
                int rr = e >> 4, cc = e & 15;
                float val = Cs[warp][rr][cc];
                int r = row0 + rr, c = col0 + cc;
                if (MODE == 1) {
                    Cout[(size_t)r*512 + c] = val + b0[c];
                } else {
                    int which = c >> 9, cm = c & 511;
                    float bias = (which == 0) ? b0[cm] : (which == 2 ? b2[cm] : 0.f);
                    float* dst = (which == 0) ? g_Q : (which == 1 ? g_K : g_V);
                    int h = cm >> 5, d = cm & 31;
                    dst[(((size_t)(r>>6)*NHD + h)*NTOK + (r&63))*HD + d] = val + bias;
                }
            }
            __syncwarp();
        }
}

// ---------------- attention: one block per (b, h) ----------------
__global__ __launch_bounds__(256) void attn_kernel(const float* __restrict__ logit_scale)
{
    __shared__ float q_s[64][36];
    __shared__ float k_s[64][36];
    __shared__ float vT [32][68];
    __shared__ float s_s[64][68];

    const int h = blockIdx.x, b = blockIdx.y;
    const int tid = threadIdx.x;
    const size_t base = ((size_t)b*NHD + h) * (NTOK*HD);
    const float* qp = g_Q + base;
    const float* kp = g_K + base;
    const float* vp = g_V + base;

    // load q,k (float4), v transposed (scalar)
    #pragma unroll
    for (int i = 0; i < 2; i++) {
        int id = tid + i*256;              // 0..511 float4 slots
        int r = id >> 3, c4 = (id & 7) << 2;
        *(float4*)&q_s[r][c4] = *(const float4*)&qp[r*32 + c4];
        *(float4*)&k_s[r][c4] = *(const float4*)&kp[r*32 + c4];
    }
    #pragma unroll
    for (int i = 0; i < 8; i++) {
        int id = tid + i*256;              // 0..2047
        int m = id >> 5, d = id & 31;
        vT[d][m] = vp[id];
    }
    __syncthreads();

    const float ls = logit_scale[h];
    const float* bp = g_bias + h*4096;

    // scores: 4x4 register tile per thread
    {
        int tn = (tid >> 4) << 2;
        int tm = (tid & 15) << 2;
        float acc[4][4] = {};
        #pragma unroll
        for (int kk = 0; kk < 32; kk += 4) {
            float4 qv[4], kv[4];
            #pragma unroll
            for (int i = 0; i < 4; i++) qv[i] = *(float4*)&q_s[tn+i][kk];
            #pragma unroll
            for (int j = 0; j < 4; j++) kv[j] = *(float4*)&k_s[tm+j][kk];
            #pragma unroll
            for (int i = 0; i < 4; i++)
                #pragma unroll
                for (int j = 0; j < 4; j++)
                    acc[i][j] += qv[i].x*kv[j].x + qv[i].y*kv[j].y
                               + qv[i].z*kv[j].z + qv[i].w*kv[j].w;
        }
        #pragma unroll
        for (int i = 0; i < 4; i++)
            #pragma unroll
            for (int j = 0; j < 4; j++)
                s_s[tn+i][tm+j] = acc[i][j]*ls + bp[(tn+i)*64 + tm+j];
    }
    __syncthreads();

    // softmax: warp handles 8 rows
    {
        int warp = tid >> 5, lane = tid & 31;
        for (int r = warp*8; r < warp*8 + 8; r++) {
            float v0 = s_s[r][lane], v1 = s_s[r][lane+32];
            float mx = fmaxf(v0, v1);
            #pragma unroll
            for (int o = 16; o; o >>= 1) mx = fmaxf(mx, __shfl_xor_sync(0xffffffffu, mx, o));
            float e0 = __expf(v0 - mx), e1 = __expf(v1 - mx);
            float sm = e0 + e1;
            #pragma unroll
            for (int o = 16; o; o >>= 1) sm += __shfl_xor_sync(0xffffffffu, sm, o);
            float inv = 1.f / sm;
            s_s[r][lane]    = e0*inv;
            s_s[r][lane+32] = e1*inv;
        }
    }
    __syncthreads();

    // AV: 2x4 register tile per thread
    {
        int d0 = (tid & 7) << 2;
        int n0 = (tid >> 3) << 1;
        float o[2][4] = {};
        #pragma unroll
        for (int m = 0; m < 64; m += 4) {
            float4 av[2], vv[4];
            #pragma unroll
            for (int i = 0; i < 2; i++) av[i] = *(float4*)&s_s[n0+i][m];
            #pragma unroll
            for (int j = 0; j < 4; j++) vv[j] = *(float4*)&vT[d0+j][m];
            #pragma unroll
            for (int i = 0; i < 2; i++)
                #pragma unroll
                for (int j = 0; j < 4; j++)
                    o[i][j] += av[i].x*vv[j].x + av[i].y*vv[j].y
                             + av[i].z*vv[j].z + av[i].w*vv[j].w;
        }
        float* op = g_attn + ((size_t)b*NTOK)*CDIM + h*HD;
        #pragma unroll
        for (int i = 0; i < 2; i++)
            #pragma unroll
            for (int j = 0; j < 4; j++)
                op[(size_t)(n0+i)*CDIM + d0 + j] = o[i][j];
    }
}

extern "C" void kernel_launch(void* const* d_in, const int* in_sizes, int n_in,
                              void* d_out, int out_size)
{
    const float* x           = (const float*)d_in[0];
    const float* qkv_w       = (const float*)d_in[1];
    const float* q_bias      = (const float*)d_in[2];
    const float* v_bias      = (const float*)d_in[3];
    const float* logit_scale = (const float*)d_in[4];
    const float* cpb_w1      = (const float*)d_in[5];
    const float* cpb_b1      = (const float*)d_in[6];
    const float* cpb_w2      = (const float*)d_in[7];
    const float* proj_w      = (const float*)d_in[8];
    const float* proj_b      = (const float*)d_in[9];
    const float* rct         = (const float*)d_in[10];
    const int*   rpi         = (const int*)d_in[11];
    float* out = (float*)d_out;

    cpb_kernel <<<225, 256>>>(rct, cpb_w1, cpb_b1, cpb_w2);
    bias_kernel<<<256, 256>>>(rpi);
    gemm128<0> <<<dim3(12, 512), 256>>>(x, qkv_w, q_bias, v_bias, nullptr);
    attn_kernel<<<dim3(NHD, BWIN), 256>>>(logit_scale);
    gemm128<1> <<<dim3(4, 512), 256>>>(nullptr, proj_w, proj_b, nullptr, out);
}

// round 6
// speedup vs baseline: 2.2295x; 2.2295x over previous
#include <cuda_runtime.h>
#include <cuda_bf16.h>
#include <mma.h>
#include <cstdint>
using namespace nvcuda;

#define BWIN 1024
#define NHD  16
#define NTOK 64
#define HD   32
#define CDIM 512
#define MROWS (BWIN*NTOK)   // 65536

// ---------------- scratch (device globals; no runtime alloc allowed) ----------------
__device__ float g_Q[BWIN*NHD*NTOK*HD];     // (b, h, n, d)
__device__ float g_K[BWIN*NHD*NTOK*HD];
__device__ float g_V[BWIN*NHD*NTOK*HD];
__device__ __nv_bfloat16 g_xhi[(size_t)MROWS*CDIM];
__device__ __nv_bfloat16 g_xlo[(size_t)MROWS*CDIM];
__device__ __nv_bfloat16 g_ahi[(size_t)MROWS*CDIM];   // attn out split (proj input)
__device__ __nv_bfloat16 g_alo[(size_t)MROWS*CDIM];
__device__ __nv_bfloat16 g_wqhi[3*CDIM*CDIM];
__device__ __nv_bfloat16 g_wqlo[3*CDIM*CDIM];
__device__ __nv_bfloat16 g_wphi[CDIM*CDIM];
__device__ __nv_bfloat16 g_wplo[CDIM*CDIM];
__device__ float g_table[225*NHD];
__device__ float g_bias[NHD*NTOK*NTOK];     // (h, n, m) = 16*sigmoid(table[idx])

// ---------------- async copy helpers ----------------
__device__ __forceinline__ void cp16(void* smem, const void* g) {
    unsigned int s = (unsigned int)__cvta_generic_to_shared(smem);
    asm volatile("cp.async.cg.shared.global [%0], [%1], 16;" :: "r"(s), "l"(g));
}
__device__ __forceinline__ void cp_commit() { asm volatile("cp.async.commit_group;"); }
template<int N>
__device__ __forceinline__ void cp_wait() { asm volatile("cp.async.wait_group %0;" :: "n"(N)); }

// ---------------- split: fp32 -> bf16 hi + bf16 lo (dest selected by template) ----------------
// DST: 0 = x -> g_xhi/g_xlo, 1 = qkv_w -> g_wqhi/g_wqlo, 2 = proj_w -> g_wphi/g_wplo
template<int DST>
__global__ void split_kernel(const float* __restrict__ src, int n4)
{
    __nv_bfloat16* hi = (DST == 0) ? g_xhi : (DST == 1 ? g_wqhi : g_wphi);
    __nv_bfloat16* lo = (DST == 0) ? g_xlo : (DST == 1 ? g_wqlo : g_wplo);
    int i = blockIdx.x*blockDim.x + threadIdx.x;
    if (i >= n4) return;
    float4 v = ((const float4*)src)[i];
    __nv_bfloat16 h[4], l[4];
    float vv[4] = {v.x, v.y, v.z, v.w};
    #pragma unroll
    for (int k = 0; k < 4; k++) {
        h[k] = __float2bfloat16(vv[k]);
        l[k] = __float2bfloat16(vv[k] - __bfloat162float(h[k]));
    }
    ((uint2*)hi)[i] = *(uint2*)h;
    ((uint2*)lo)[i] = *(uint2*)l;
}

// ---------------- kernel 1: CPB MLP -> table (225, 16) ----------------
__global__ void cpb_kernel(const float* __restrict__ rct, const float* __restrict__ w1,
                           const float* __restrict__ b1, const float* __restrict__ w2)
{
    __shared__ float hid[512];
    int t = blockIdx.x;
    float c0 = rct[t*2], c1 = rct[t*2+1];
    for (int j = threadIdx.x; j < 512; j += blockDim.x) {
        float hv = c0*w1[j*2] + c1*w1[j*2+1] + b1[j];
        hid[j] = hv > 0.f ? hv : 0.f;
    }
    __syncthreads();
    int warp = threadIdx.x >> 5, lane = threadIdx.x & 31;
    for (int h = warp; h < NHD; h += 8) {
        float s = 0.f;
        for (int j = lane; j < 512; j += 32) s += hid[j]*w2[h*512 + j];
        #pragma unroll
        for (int o = 16; o; o >>= 1) s += __shfl_xor_sync(0xffffffffu, s, o);
        if (lane == 0) g_table[t*NHD + h] = s;
    }
}

// ---------------- kernel 2: rel-pos bias (16, 64, 64) ----------------
__global__ void bias_kernel(const int* __restrict__ idx)
{
    int i = blockIdx.x*blockDim.x + threadIdx.x;
    int h = i >> 12;
    int nm = i & 4095;
    float v = g_table[idx[nm]*NHD + h];
    g_bias[i] = 16.f / (1.f + __expf(-v));
}

// ---------------- bf16x3 GEMM: C(M,N) = A(M,512) * Bw(N,512)^T ----------------
// A = Ahi + Alo, B = Bhi + Blo (bf16 pairs). C ~= Ah*Bh + Al*Bh + Ah*Bl.
// 128x128 block tile, k-tile 16, cp.async double buffer.
// MODE 0: A=x split, B=qkv_w split; scatter to g_Q/g_K/g_V with [q_bias, 0, v_bias]
// MODE 1: A=attn split, B=proj_w split; out + b0
#define KT 16
#define TSTRIDE 24                 // bf16 elems per row (16 + 8 pad)
#define TILE_E (128*TSTRIDE)       // 3072 elems = 6144 B

template<int MODE>
__global__ __launch_bounds__(256) void gemm128(
        const float* __restrict__ b0, const float* __restrict__ b2,
        float* __restrict__ Cout)
{
    // 2 stages x 4 tiles (Ahi, Alo, Bhi, Blo) = 49152 B
    __shared__ __align__(16) __nv_bfloat16 sm[2*4*TILE_E];

    const __nv_bfloat16* gsrc[4];
    if (MODE == 0) { gsrc[0] = g_xhi; gsrc[1] = g_xlo; gsrc[2] = g_wqhi; gsrc[3] = g_wqlo; }
    else           { gsrc[0] = g_ahi; gsrc[1] = g_alo; gsrc[2] = g_wphi; gsrc[3] = g_wplo; }

    const int tid  = threadIdx.x;
    const int warp = tid >> 5, lane = tid & 31;
    const int warpM = warp >> 2, warpN = warp & 3;     // 2 x 4 warp grid
    const int m0 = blockIdx.y * 128;
    const int n0 = blockIdx.x * 128;

    wmma::fragment<wmma::accumulator,16,16,16,float> acc[4][2];
    #pragma unroll
    for (int i=0;i<4;i++)
        #pragma unroll
        for (int j=0;j<2;j++) wmma::fill_fragment(acc[i][j], 0.f);

    auto prefetch = [&](int stage, int kt) {
        __nv_bfloat16* base = sm + stage*4*TILE_E;
        #pragma unroll
        for (int c = 0; c < 4; c++) {
            int chunk = tid + c*256;
            int tile = chunk >> 8;
            int r    = (chunk & 255) >> 1;
            int half = chunk & 1;
            int grow = (tile < 2) ? (m0 + r) : (n0 + r);
            const __nv_bfloat16* g = gsrc[tile] + (size_t)grow*512 + kt + half*8;
            cp16(base + tile*TILE_E + r*TSTRIDE + half*8, g);
        }
        cp_commit();
    };

    prefetch(0, 0);
    #pragma unroll 1
    for (int it = 0; it < 512/KT; it++) {
        if (it + 1 < 512/KT) { prefetch((it+1)&1, (it+1)*KT); cp_wait<1>(); }
        else                 { cp_wait<0>(); }
        __syncthreads();

        const __nv_bfloat16* st = sm + (it&1)*4*TILE_E;
        wmma::fragment<wmma::matrix_a,16,16,16,__nv_bfloat16,wmma::row_major> ah[4], al[4];
        wmma::fragment<wmma::matrix_b,16,16,16,__nv_bfloat16,wmma::col_major> bh[2], bl[2];
        #pragma unroll
        for (int i = 0; i < 4; i++) {
            wmma::load_matrix_sync(ah[i], st + 0*TILE_E + (warpM*64 + i*16)*TSTRIDE, TSTRIDE);
            wmma::load_matrix_sync(al[i], st + 1*TILE_E + (warpM*64 + i*16)*TSTRIDE, TSTRIDE);
        }
        #pragma unroll
        for (int j = 0; j < 2; j++) {
            wmma::load_matrix_sync(bh[j], st + 2*TILE_E + (warpN*32 + j*16)*TSTRIDE, TSTRIDE);
            wmma::load_matrix_sync(bl[j], st + 3*TILE_E + (warpN*32 + j*16)*TSTRIDE, TSTRIDE);
        }
        #pragma unroll
        for (int i = 0; i < 4; i++)
            #pragma unroll
            for (int j = 0; j < 2; j++) {
                wmma::mma_sync(acc[i][j], al[i], bh[j], acc[i][j]);
                wmma::mma_sync(acc[i][j], ah[i], bl[j], acc[i][j]);
                wmma::mma_sync(acc[i][j], ah[i], bh[j], acc[i][j]);
            }
        __syncthreads();
    }

    // epilogue: alias smem as per-warp 16x16 staging
    float* Cs = (float*)sm + warp*256;
    #pragma unroll
    for (int i = 0; i < 4; i++)
        #pragma unroll
        for (int j = 0; j < 2; j++) {
            wmma::store_matrix_sync(Cs, acc[i][j], 16, wmma::mem_row_major);
            __syncwarp();
            int row0 = m0 + warpM*64 + i*16;
            int col0 = n0 + warpN*32 + j*16;
            #pragma unroll
            for (int e = lane; e < 256; e += 32) {
                int rr = e >> 4, cc = e & 15;
                float val = Cs[rr*16 + cc];
                int r = row0 + rr, c = col0 + cc;
                if (MODE == 1) {
                    Cout[(size_t)r*512 + c] = val + b0[c];
                } else {
                    int which = c >> 9, cm = c & 511;
                    float bias = (which == 0) ? b0[cm] : (which == 2 ? b2[cm] : 0.f);
                    float* dst = (which == 0) ? g_Q : (which == 1 ? g_K : g_V);
                    int h = cm >> 5, d = cm & 31;
                    dst[(((size_t)(r>>6)*NHD + h)*NTOK + (r&63))*HD + d] = val + bias;
                }
            }
            __syncwarp();
        }
}

// ---------------- attention: one block per (b, h) ----------------
__global__ __launch_bounds__(256) void attn_kernel(const float* __restrict__ logit_scale)
{
    __shared__ float q_s[64][36];
    __shared__ float k_s[64][36];
    __shared__ float vT [32][68];
    __shared__ float s_s[64][68];

    const int h = blockIdx.x, b = blockIdx.y;
    const int tid = threadIdx.x;
    const size_t base = ((size_t)b*NHD + h) * (NTOK*HD);
    const float* qp = g_Q + base;
    const float* kp = g_K + base;
    const float* vp = g_V + base;

    #pragma unroll
    for (int i = 0; i < 2; i++) {
        int id = tid + i*256;
        int r = id >> 3, c4 = (id & 7) << 2;
        *(float4*)&q_s[r][c4] = *(const float4*)&qp[r*32 + c4];
        *(float4*)&k_s[r][c4] = *(const float4*)&kp[r*32 + c4];
    }
    #pragma unroll
    for (int i = 0; i < 8; i++) {
        int id = tid + i*256;
        int m = id >> 5, d = id & 31;
        vT[d][m] = vp[id];
    }
    __syncthreads();

    const float ls = logit_scale[h];
    const float* bp = g_bias + h*4096;

    {
        int tn = (tid >> 4) << 2;
        int tm = (tid & 15) << 2;
        float acc[4][4] = {};
        #pragma unroll
        for (int kk = 0; kk < 32; kk += 4) {
            float4 qv[4], kv[4];
            #pragma unroll
            for (int i = 0; i < 4; i++) qv[i] = *(float4*)&q_s[tn+i][kk];
            #pragma unroll
            for (int j = 0; j < 4; j++) kv[j] = *(float4*)&k_s[tm+j][kk];
            #pragma unroll
            for (int i = 0; i < 4; i++)
                #pragma unroll
                for (int j = 0; j < 4; j++)
                    acc[i][j] += qv[i].x*kv[j].x + qv[i].y*kv[j].y
                               + qv[i].z*kv[j].z + qv[i].w*kv[j].w;
        }
        #pragma unroll
        for (int i = 0; i < 4; i++)
            #pragma unroll
            for (int j = 0; j < 4; j++)
                s_s[tn+i][tm+j] = acc[i][j]*ls + bp[(tn+i)*64 + tm+j];
    }
    __syncthreads();

    {
        int warp = tid >> 5, lane = tid & 31;
        for (int r = warp*8; r < warp*8 + 8; r++) {
            float v0 = s_s[r][lane], v1 = s_s[r][lane+32];
            float mx = fmaxf(v0, v1);
            #pragma unroll
            for (int o = 16; o; o >>= 1) mx = fmaxf(mx, __shfl_xor_sync(0xffffffffu, mx, o));
            float e0 = __expf(v0 - mx), e1 = __expf(v1 - mx);
            float sm = e0 + e1;
            #pragma unroll
            for (int o = 16; o; o >>= 1) sm += __shfl_xor_sync(0xffffffffu, sm, o);
            float inv = 1.f / sm;
            s_s[r][lane]    = e0*inv;
            s_s[r][lane+32] = e1*inv;
        }
    }
    __syncthreads();

    {
        int d0 = (tid & 7) << 2;
        int n0 = (tid >> 3) << 1;
        float o[2][4] = {};
        #pragma unroll
        for (int m = 0; m < 64; m += 4) {
            float4 av[2], vv[4];
            #pragma unroll
            for (int i = 0; i < 2; i++) av[i] = *(float4*)&s_s[n0+i][m];
            #pragma unroll
            for (int j = 0; j < 4; j++) vv[j] = *(float4*)&vT[d0+j][m];
            #pragma unroll
            for (int i = 0; i < 2; i++)
                #pragma unroll
                for (int j = 0; j < 4; j++)
                    o[i][j] += av[i].x*vv[j].x + av[i].y*vv[j].y
                             + av[i].z*vv[j].z + av[i].w*vv[j].w;
        }
        // write proj input pre-split into bf16 hi/lo
        size_t ro = ((size_t)b*NTOK)*CDIM + h*HD;
        #pragma unroll
        for (int i = 0; i < 2; i++)
            #pragma unroll
            for (int j = 0; j < 4; j++) {
                float v = o[i][j];
                __nv_bfloat16 hh = __float2bfloat16(v);
                __nv_bfloat16 ll = __float2bfloat16(v - __bfloat162float(hh));
                size_t addr = ro + (size_t)(n0+i)*CDIM + d0 + j;
                g_ahi[addr] = hh;
                g_alo[addr] = ll;
            }
    }
}

extern "C" void kernel_launch(void* const* d_in, const int* in_sizes, int n_in,
                              void* d_out, int out_size)
{
    const float* x           = (const float*)d_in[0];
    const float* qkv_w       = (const float*)d_in[1];
    const float* q_bias      = (const float*)d_in[2];
    const float* v_bias      = (const float*)d_in[3];
    const float* logit_scale = (const float*)d_in[4];
    const float* cpb_w1      = (const float*)d_in[5];
    const float* cpb_b1      = (const float*)d_in[6];
    const float* cpb_w2      = (const float*)d_in[7];
    const float* proj_w      = (const float*)d_in[8];
    const float* proj_b      = (const float*)d_in[9];
    const float* rct         = (const float*)d_in[10];
    const int*   rpi         = (const int*)d_in[11];
    float* out = (float*)d_out;

    {
        int n4 = MROWS*CDIM/4;
        split_kernel<0><<<(n4+255)/256, 256>>>(x, n4);
        n4 = 3*CDIM*CDIM/4;
        split_kernel<1><<<(n4+255)/256, 256>>>(qkv_w, n4);
        n4 = CDIM*CDIM/4;
        split_kernel<2><<<(n4+255)/256, 256>>>(proj_w, n4);
    }
    cpb_kernel <<<225, 256>>>(rct, cpb_w1, cpb_b1, cpb_w2);
    bias_kernel<<<256, 256>>>(rpi);
    gemm128<0> <<<dim3(12, 512), 256>>>(q_bias, v_bias, nullptr);
    attn_kernel<<<dim3(NHD, BWIN), 256>>>(logit_scale);
    gemm128<1> <<<dim3(4, 512), 256>>>(proj_b, nullptr, out);
}

// round 7
// speedup vs baseline: 2.8751x; 1.2896x over previous
#include <cuda_runtime.h>
#include <cuda_bf16.h>
#include <mma.h>
#include <cstdint>
using namespace nvcuda;

#define BWIN 1024
#define NHD  16
#define NTOK 64
#define HD   32
#define CDIM 512
#define MROWS (BWIN*NTOK)   // 65536

// ---------------- scratch (device globals; no runtime alloc allowed) ----------------
__device__ __nv_bfloat16 g_qhi[(size_t)BWIN*NHD*NTOK*HD];   // (b,h,n,d) bf16 pairs
__device__ __nv_bfloat16 g_qlo[(size_t)BWIN*NHD*NTOK*HD];
__device__ __nv_bfloat16 g_khi[(size_t)BWIN*NHD*NTOK*HD];
__device__ __nv_bfloat16 g_klo[(size_t)BWIN*NHD*NTOK*HD];
__device__ __nv_bfloat16 g_vhi[(size_t)BWIN*NHD*NTOK*HD];
__device__ __nv_bfloat16 g_vlo[(size_t)BWIN*NHD*NTOK*HD];
__device__ __nv_bfloat16 g_xhi[(size_t)MROWS*CDIM];
__device__ __nv_bfloat16 g_xlo[(size_t)MROWS*CDIM];
__device__ __nv_bfloat16 g_ahi[(size_t)MROWS*CDIM];   // attn out split (proj input)
__device__ __nv_bfloat16 g_alo[(size_t)MROWS*CDIM];
__device__ __nv_bfloat16 g_wqhi[3*CDIM*CDIM];
__device__ __nv_bfloat16 g_wqlo[3*CDIM*CDIM];
__device__ __nv_bfloat16 g_wphi[CDIM*CDIM];
__device__ __nv_bfloat16 g_wplo[CDIM*CDIM];
__device__ float g_table[225*NHD];
__device__ float g_bias[NHD*NTOK*NTOK];     // (h, n, m) = 16*sigmoid(table[idx])

// ---------------- async copy helpers ----------------
__device__ __forceinline__ void cp16(void* smem, const void* g) {
    unsigned int s = (unsigned int)__cvta_generic_to_shared(smem);
    asm volatile("cp.async.cg.shared.global [%0], [%1], 16;" :: "r"(s), "l"(g));
}
__device__ __forceinline__ void cp_commit() { asm volatile("cp.async.commit_group;"); }
template<int N>
__device__ __forceinline__ void cp_wait() { asm volatile("cp.async.wait_group %0;" :: "n"(N)); }

// ---------------- split: fp32 -> bf16 hi + bf16 lo (dest selected by template) ----------------
template<int DST>
__global__ void split_kernel(const float* __restrict__ src, int n4)
{
    __nv_bfloat16* hi = (DST == 0) ? g_xhi : (DST == 1 ? g_wqhi : g_wphi);
    __nv_bfloat16* lo = (DST == 0) ? g_xlo : (DST == 1 ? g_wqlo : g_wplo);
    int i = blockIdx.x*blockDim.x + threadIdx.x;
    if (i >= n4) return;
    float4 v = ((const float4*)src)[i];
    __nv_bfloat16 h[4], l[4];
    float vv[4] = {v.x, v.y, v.z, v.w};
    #pragma unroll
    for (int k = 0; k < 4; k++) {
        h[k] = __float2bfloat16(vv[k]);
        l[k] = __float2bfloat16(vv[k] - __bfloat162float(h[k]));
    }
    ((uint2*)hi)[i] = *(uint2*)h;
    ((uint2*)lo)[i] = *(uint2*)l;
}

// ---------------- kernel 1: CPB MLP -> table (225, 16) ----------------
__global__ void cpb_kernel(const float* __restrict__ rct, const float* __restrict__ w1,
                           const float* __restrict__ b1, const float* __restrict__ w2)
{
    __shared__ float hid[512];
    int t = blockIdx.x;
    float c0 = rct[t*2], c1 = rct[t*2+1];
    for (int j = threadIdx.x; j < 512; j += blockDim.x) {
        float hv = c0*w1[j*2] + c1*w1[j*2+1] + b1[j];
        hid[j] = hv > 0.f ? hv : 0.f;
    }
    __syncthreads();
    int warp = threadIdx.x >> 5, lane = threadIdx.x & 31;
    for (int h = warp; h < NHD; h += 8) {
        float s = 0.f;
        for (int j = lane; j < 512; j += 32) s += hid[j]*w2[h*512 + j];
        #pragma unroll
        for (int o = 16; o; o >>= 1) s += __shfl_xor_sync(0xffffffffu, s, o);
        if (lane == 0) g_table[t*NHD + h] = s;
    }
}

// ---------------- kernel 2: rel-pos bias (16, 64, 64) ----------------
__global__ void bias_kernel(const int* __restrict__ idx)
{
    int i = blockIdx.x*blockDim.x + threadIdx.x;
    int h = i >> 12;
    int nm = i & 4095;
    float v = g_table[idx[nm]*NHD + h];
    g_bias[i] = 16.f / (1.f + __expf(-v));
}

// ---------------- bf16x3 GEMM: C(M,N) = A(M,512) * Bw(N,512)^T ----------------
#define KT 16
#define TSTRIDE 24
#define TILE_E (128*TSTRIDE)

template<int MODE>
__global__ __launch_bounds__(256) void gemm128(
        const float* __restrict__ b0, const float* __restrict__ b2,
        float* __restrict__ Cout)
{
    __shared__ __align__(16) __nv_bfloat16 sm[2*4*TILE_E];

    const __nv_bfloat16* gsrc[4];
    if (MODE == 0) { gsrc[0] = g_xhi; gsrc[1] = g_xlo; gsrc[2] = g_wqhi; gsrc[3] = g_wqlo; }
    else           { gsrc[0] = g_ahi; gsrc[1] = g_alo; gsrc[2] = g_wphi; gsrc[3] = g_wplo; }

    const int tid  = threadIdx.x;
    const int warp = tid >> 5, lane = tid & 31;
    const int warpM = warp >> 2, warpN = warp & 3;
    const int m0 = blockIdx.y * 128;
    const int n0 = blockIdx.x * 128;

    wmma::fragment<wmma::accumulator,16,16,16,float> acc[4][2];
    #pragma unroll
    for (int i=0;i<4;i++)
        #pragma unroll
        for (int j=0;j<2;j++) wmma::fill_fragment(acc[i][j], 0.f);

    auto prefetch = [&](int stage, int kt) {
        __nv_bfloat16* base = sm + stage*4*TILE_E;
        #pragma unroll
        for (int c = 0; c < 4; c++) {
            int chunk = tid + c*256;
            int tile = chunk >> 8;
            int r    = (chunk & 255) >> 1;
            int half = chunk & 1;
            int grow = (tile < 2) ? (m0 + r) : (n0 + r);
            const __nv_bfloat16* g = gsrc[tile] + (size_t)grow*512 + kt + half*8;
            cp16(base + tile*TILE_E + r*TSTRIDE + half*8, g);
        }
        cp_commit();
    };

    prefetch(0, 0);
    #pragma unroll 1
    for (int it = 0; it < 512/KT; it++) {
        if (it + 1 < 512/KT) { prefetch((it+1)&1, (it+1)*KT); cp_wait<1>(); }
        else                 { cp_wait<0>(); }
        __syncthreads();

        const __nv_bfloat16* st = sm + (it&1)*4*TILE_E;
        wmma::fragment<wmma::matrix_a,16,16,16,__nv_bfloat16,wmma::row_major> ah[4], al[4];
        wmma::fragment<wmma::matrix_b,16,16,16,__nv_bfloat16,wmma::col_major> bh[2], bl[2];
        #pragma unroll
        for (int i = 0; i < 4; i++) {
            wmma::load_matrix_sync(ah[i], st + 0*TILE_E + (warpM*64 + i*16)*TSTRIDE, TSTRIDE);
            wmma::load_matrix_sync(al[i], st + 1*TILE_E + (warpM*64 + i*16)*TSTRIDE, TSTRIDE);
        }
        #pragma unroll
        for (int j = 0; j < 2; j++) {
            wmma::load_matrix_sync(bh[j], st + 2*TILE_E + (warpN*32 + j*16)*TSTRIDE, TSTRIDE);
            wmma::load_matrix_sync(bl[j], st + 3*TILE_E + (warpN*32 + j*16)*TSTRIDE, TSTRIDE);
        }
        #pragma unroll
        for (int i = 0; i < 4; i++)
            #pragma unroll
            for (int j = 0; j < 2; j++) {
                wmma::mma_sync(acc[i][j], al[i], bh[j], acc[i][j]);
                wmma::mma_sync(acc[i][j], ah[i], bl[j], acc[i][j]);
                wmma::mma_sync(acc[i][j], ah[i], bh[j], acc[i][j]);
            }
        __syncthreads();
    }

    float* Cs = (float*)sm + warp*256;
    #pragma unroll
    for (int i = 0; i < 4; i++)
        #pragma unroll
        for (int j = 0; j < 2; j++) {
            wmma::store_matrix_sync(Cs, acc[i][j], 16, wmma::mem_row_major);
            __syncwarp();
            int row0 = m0 + warpM*64 + i*16;
            int col0 = n0 + warpN*32 + j*16;
            #pragma unroll
            for (int e = lane; e < 256; e += 32) {
                int rr = e >> 4, cc = e & 15;
                float val = Cs[rr*16 + cc];
                int r = row0 + rr, c = col0 + cc;
                if (MODE == 1) {
                    Cout[(size_t)r*512 + c] = val + b0[c];
                } else {
                    int which = c >> 9, cm = c & 511;
                    float bias = (which == 0) ? b0[cm] : (which == 2 ? b2[cm] : 0.f);
                    __nv_bfloat16* dhi = (which == 0) ? g_qhi : (which == 1 ? g_khi : g_vhi);
                    __nv_bfloat16* dlo = (which == 0) ? g_qlo : (which == 1 ? g_klo : g_vlo);
                    int h = cm >> 5, d = cm & 31;
                    size_t idx = (((size_t)(r>>6)*NHD + h)*NTOK + (r&63))*HD + d;
                    float v = val + bias;
                    __nv_bfloat16 hh = __float2bfloat16(v);
                    dhi[idx] = hh;
                    dlo[idx] = __float2bfloat16(v - __bfloat162float(hh));
                }
            }
            __syncwarp();
        }
}

// ---------------- attention v2: bf16x3 tensor cores, one block per (b, h) ----------------
// smem layout (bytes):
//  0      Qhi 64x40 bf16 (5120)     [overlaid later by Phi 64x72 bf16 (9216)]
//  5120   Qlo 64x40 bf16            [overlaid by Plo (9216) @ 9216..18432]
//  10240  Khi 64x40 bf16
//  15360  Klo 64x40 bf16
//  20480  Vhi 64x40 bf16
//  25600  Vlo 64x40 bf16
//  30720  S   64x68 fp32 (17408)
#define AS_QH 0
#define AS_QL 5120
#define AS_KH 10240
#define AS_KL 15360
#define AS_VH 20480
#define AS_VL 25600
#define AS_S  30720
#define AS_PH 0
#define AS_PL 9216
#define AS_TOTAL 48128
#define LDB 40
#define LDS_F 68
#define LDP 72

__global__ __launch_bounds__(128) void attn_kernel(const float* __restrict__ logit_scale)
{
    __shared__ __align__(16) char smem[AS_TOTAL];

    const int h = blockIdx.x, b = blockIdx.y;
    const int tid  = threadIdx.x;
    const int w    = tid >> 5, lane = tid & 31;
    const size_t base = ((size_t)b*NHD + h) * (NTOK*HD);

    // ---- load 6 bf16 tiles via cp.async ----
    {
        const __nv_bfloat16* garr[6] = {g_qhi+base, g_qlo+base, g_khi+base,
                                        g_klo+base, g_vhi+base, g_vlo+base};
        const int soff[6] = {AS_QH, AS_QL, AS_KH, AS_KL, AS_VH, AS_VL};
        #pragma unroll
        for (int i = 0; i < 12; i++) {
            int c = tid + i*128;             // 0..1535
            int a  = c >> 8;
            int cc = c & 255;
            int n  = cc >> 2, d8 = (cc & 3) * 8;
            cp16(smem + soff[a] + (n*LDB + d8)*2, garr[a] + n*HD + d8);
        }
        cp_commit(); cp_wait<0>();
    }
    __syncthreads();

    // ---- scores = QK^T (bf16x3), warp w owns rows w*16..w*16+15 ----
    {
        const __nv_bfloat16* Qh = (const __nv_bfloat16*)(smem + AS_QH);
        const __nv_bfloat16* Ql = (const __nv_bfloat16*)(smem + AS_QL);
        const __nv_bfloat16* Kh = (const __nv_bfloat16*)(smem + AS_KH);
        const __nv_bfloat16* Kl = (const __nv_bfloat16*)(smem + AS_KL);
        float* S = (float*)(smem + AS_S);

        wmma::fragment<wmma::accumulator,16,16,16,float> sacc[4];
        #pragma unroll
        for (int j = 0; j < 4; j++) wmma::fill_fragment(sacc[j], 0.f);

        #pragma unroll
        for (int kk = 0; kk < 2; kk++) {
            wmma::fragment<wmma::matrix_a,16,16,16,__nv_bfloat16,wmma::row_major> ah, al;
            wmma::load_matrix_sync(ah, Qh + (w*16)*LDB + kk*16, LDB);
            wmma::load_matrix_sync(al, Ql + (w*16)*LDB + kk*16, LDB);
            #pragma unroll
            for (int j = 0; j < 4; j++) {
                wmma::fragment<wmma::matrix_b,16,16,16,__nv_bfloat16,wmma::col_major> bh, bl;
                wmma::load_matrix_sync(bh, Kh + (j*16)*LDB + kk*16, LDB);
                wmma::load_matrix_sync(bl, Kl + (j*16)*LDB + kk*16, LDB);
                wmma::mma_sync(sacc[j], al, bh, sacc[j]);
                wmma::mma_sync(sacc[j], ah, bl, sacc[j]);
                wmma::mma_sync(sacc[j], ah, bh, sacc[j]);
            }
        }
        #pragma unroll
        for (int j = 0; j < 4; j++)
            wmma::store_matrix_sync(S + (w*16)*LDS_F + j*16, sacc[j], LDS_F, wmma::mem_row_major);
    }
    __syncthreads();

    // ---- softmax (fused *ls + bias), emit P as bf16 hi/lo over Q/K smem ----
    {
        const float ls = logit_scale[h];
        const float* bp = g_bias + h*4096;
        float* S = (float*)(smem + AS_S);
        __nv_bfloat16* Ph = (__nv_bfloat16*)(smem + AS_PH);
        __nv_bfloat16* Pl = (__nv_bfloat16*)(smem + AS_PL);

        #pragma unroll 4
        for (int rr = 0; rr < 16; rr++) {
            int r = w*16 + rr;
            float v0 = S[r*LDS_F + lane]      * ls + bp[r*64 + lane];
            float v1 = S[r*LDS_F + 32 + lane] * ls + bp[r*64 + 32 + lane];
            float mx = fmaxf(v0, v1);
            #pragma unroll
            for (int o = 16; o; o >>= 1) mx = fmaxf(mx, __shfl_xor_sync(0xffffffffu, mx, o));
            float e0 = __expf(v0 - mx), e1 = __expf(v1 - mx);
            float s = e0 + e1;
            #pragma unroll
            for (int o = 16; o; o >>= 1) s += __shfl_xor_sync(0xffffffffu, s, o);
            float inv = 1.f / s;
            float p0 = e0*inv, p1 = e1*inv;
            __nv_bfloat16 h0 = __float2bfloat16(p0);
            __nv_bfloat16 h1 = __float2bfloat16(p1);
            Ph[r*LDP + lane]      = h0;
            Ph[r*LDP + 32 + lane] = h1;
            Pl[r*LDP + lane]      = __float2bfloat16(p0 - __bfloat162float(h0));
            Pl[r*LDP + 32 + lane] = __float2bfloat16(p1 - __bfloat162float(h1));
        }
    }
    __syncthreads();

    // ---- out = P @ V (bf16x3), warp w owns rows w*16..w*16+15 ----
    {
        const __nv_bfloat16* Ph = (const __nv_bfloat16*)(smem + AS_PH);
        const __nv_bfloat16* Pl = (const __nv_bfloat16*)(smem + AS_PL);
        const __nv_bfloat16* Vh = (const __nv_bfloat16*)(smem + AS_VH);
        const __nv_bfloat16* Vl = (const __nv_bfloat16*)(smem + AS_VL);
        float* S = (float*)(smem + AS_S);

        wmma::fragment<wmma::accumulator,16,16,16,float> oacc[2];
        #pragma unroll
        for (int j = 0; j < 2; j++) wmma::fill_fragment(oacc[j], 0.f);

        #pragma unroll
        for (int kk = 0; kk < 4; kk++) {
            wmma::fragment<wmma::matrix_a,16,16,16,__nv_bfloat16,wmma::row_major> ph, pl;
            wmma::load_matrix_sync(ph, Ph + (w*16)*LDP + kk*16, LDP);
            wmma::load_matrix_sync(pl, Pl + (w*16)*LDP + kk*16, LDP);
            #pragma unroll
            for (int j = 0; j < 2; j++) {
                wmma::fragment<wmma::matrix_b,16,16,16,__nv_bfloat16,wmma::row_major> vh, vl;
                wmma::load_matrix_sync(vh, Vh + (kk*16)*LDB + j*16, LDB);
                wmma::load_matrix_sync(vl, Vl + (kk*16)*LDB + j*16, LDB);
                wmma::mma_sync(oacc[j], pl, vh, oacc[j]);
                wmma::mma_sync(oacc[j], ph, vl, oacc[j]);
                wmma::mma_sync(oacc[j], ph, vh, oacc[j]);
            }
        }
        __syncthreads();   // S no longer needed as scores
        #pragma unroll
        for (int j = 0; j < 2; j++)
            wmma::store_matrix_sync(S + (w*16)*LDS_F + j*16, oacc[j], LDS_F, wmma::mem_row_major);
    }
    __syncthreads();

    // ---- write proj input split into g_ahi/g_alo ----
    {
        const float* S = (const float*)(smem + AS_S);
        int r = tid >> 1, half = tid & 1;
        const float* srow = S + r*LDS_F + half*16;
        __nv_bfloat16 hi16[16], lo16[16];
        #pragma unroll
        for (int i = 0; i < 16; i++) {
            float v = srow[i];
            __nv_bfloat16 hh = __float2bfloat16(v);
            hi16[i] = hh;
            lo16[i] = __float2bfloat16(v - __bfloat162float(hh));
        }
        size_t o = ((size_t)(b*NTOK + r))*CDIM + h*HD + half*16;
        ((uint4*)(g_ahi + o))[0] = ((uint4*)hi16)[0];
        ((uint4*)(g_ahi + o))[1] = ((uint4*)hi16)[1];
        ((uint4*)(g_alo + o))[0] = ((uint4*)lo16)[0];
        ((uint4*)(g_alo + o))[1] = ((uint4*)lo16)[1];
    }
}

extern "C" void kernel_launch(void* const* d_in, const int* in_sizes, int n_in,
                              void* d_out, int out_size)
{
    const float* x           = (const float*)d_in[0];
    const float* qkv_w       = (const float*)d_in[1];
    const float* q_bias      = (const float*)d_in[2];
    const float* v_bias      = (const float*)d_in[3];
    const float* logit_scale = (const float*)d_in[4];
    const float* cpb_w1      = (const float*)d_in[5];
    const float* cpb_b1      = (const float*)d_in[6];
    const float* cpb_w2      = (const float*)d_in[7];
    const float* proj_w      = (const float*)d_in[8];
    const float* proj_b      = (const float*)d_in[9];
    const float* rct         = (const float*)d_in[10];
    const int*   rpi         = (const int*)d_in[11];
    float* out = (float*)d_out;

    {
        int n4 = MROWS*CDIM/4;
        split_kernel<0><<<(n4+255)/256, 256>>>(x, n4);
        n4 = 3*CDIM*CDIM/4;
        split_kernel<1><<<(n4+255)/256, 256>>>(qkv_w, n4);
        n4 = CDIM*CDIM/4;
        split_kernel<2><<<(n4+255)/256, 256>>>(proj_w, n4);
    }
    cpb_kernel <<<225, 256>>>(rct, cpb_w1, cpb_b1, cpb_w2);
    bias_kernel<<<256, 256>>>(rpi);
    gemm128<0> <<<dim3(12, 512), 256>>>(q_bias, v_bias, nullptr);
    attn_kernel<<<dim3(NHD, BWIN), 128>>>(logit_scale);
    gemm128<1> <<<dim3(4, 512), 256>>>(proj_b, nullptr, out);
}